// round 6
// baseline (speedup 1.0000x reference)
#include <cuda_runtime.h>
#include <cstdint>

#define NB 4
#define NPTS 262144
#define NPTS_LOG2 18
#define KTOP 6000
#define CAP 16384
#define NOUT 1000
#define NBINS 65536
#define NMS_T 1024
#define THR 0.7f

// ---------------- device scratch (no allocations allowed) ----------------
__device__ unsigned int g_hist[NB * NBINS];
__device__ unsigned int g_cnt[NB];
__device__ unsigned int g_cut[NB];
__device__ unsigned long long g_cand[NB * CAP];
__device__ float4 g_boxes[NB * KTOP];

// ---------------- zero scratch (graph replays reuse it) ----------------
__global__ void k_zero() {
    int stride = gridDim.x * blockDim.x;
    for (int i = blockIdx.x * blockDim.x + threadIdx.x; i < NB * NBINS; i += stride)
        g_hist[i] = 0;
    if (blockIdx.x == 0 && threadIdx.x < NB) g_cnt[threadIdx.x] = 0;
}

// ---------------- histogram of top-16 float bits of fg score ----------------
__global__ void k_hist(const float* __restrict__ scores) {
    int idx = blockIdx.x * blockDim.x + threadIdx.x;
    if (idx >= NB * NPTS) return;
    float s = scores[(size_t)idx * 2 + 1];
    unsigned bin = __float_as_uint(s) >> 16;   // scores in [0,1): bits monotone
    int b = idx >> NPTS_LOG2;
    atomicAdd(&g_hist[b * NBINS + bin], 1u);
}

// ---------------- find exact cutoff bin: max c with suffix(c) >= KTOP ----------------
__global__ void k_cut() {
    __shared__ unsigned int csum[1024];
    int b = blockIdx.x, t = threadIdx.x;
    const unsigned int* h = &g_hist[b * NBINS];
    unsigned int s = 0;
#pragma unroll
    for (int j = 0; j < 64; j++) s += h[t * 64 + j];
    csum[t] = s;
    __syncthreads();
    if (t == 0) {
        unsigned int run = 0;
        unsigned int cut = 0;
        for (int c = 1023; c >= 0; c--) {
            if (run + csum[c] >= KTOP) {
                unsigned int r2 = run;
                for (int bin = c * 64 + 63; bin >= c * 64; bin--) {
                    r2 += h[bin];
                    if (r2 >= KTOP) { cut = (unsigned)bin; break; }
                }
                g_cut[b] = cut;
                return;
            }
            run += csum[c];
        }
        g_cut[b] = 0;
    }
}

// ---------------- compact candidates above cutoff ----------------
__global__ void k_compact(const float* __restrict__ scores) {
    int idx = blockIdx.x * blockDim.x + threadIdx.x;
    if (idx >= NB * NPTS) return;
    float s = scores[(size_t)idx * 2 + 1];
    unsigned bits = __float_as_uint(s);
    unsigned bin = bits >> 16;
    int b = idx >> NPTS_LOG2;
    if (bin >= g_cut[b]) {
        unsigned pos = atomicAdd(&g_cnt[b], 1u);
        if (pos < CAP) {
            unsigned i = (unsigned)idx & (NPTS - 1);
            // key: score desc, then index asc (JAX top_k tie order), bit-exact
            g_cand[b * CAP + pos] = ((unsigned long long)bits << 32) | (unsigned)(~i);
        }
    }
}

// ---------------- bitonic sort 16384 keys (desc) + box decode ----------------
__global__ void k_sort(const float* __restrict__ deltas, const float* __restrict__ anchors) {
    extern __shared__ unsigned long long sk[];
    int b = blockIdx.x, t = threadIdx.x;
    unsigned int n = g_cnt[b];
    if (n > CAP) n = CAP;
    for (int i = t; i < CAP; i += blockDim.x)
        sk[i] = (i < (int)n) ? g_cand[b * CAP + i] : 0ULL;
    __syncthreads();
    for (int k = 2; k <= CAP; k <<= 1) {
        for (int j = k >> 1; j > 0; j >>= 1) {
            for (int i = t; i < CAP; i += blockDim.x) {
                int ixj = i ^ j;
                if (ixj > i) {
                    unsigned long long a = sk[i], c = sk[ixj];
                    bool sw = ((i & k) == 0) ? (a < c) : (a > c);  // descending
                    if (sw) { sk[i] = c; sk[ixj] = a; }
                }
            }
            __syncthreads();
        }
    }
    // decode top KTOP boxes
    for (int r = t; r < KTOP; r += blockDim.x) {
        float4 box = make_float4(0.f, 0.f, 0.f, 0.f);
        if (r < (int)n) {
            unsigned long long key = sk[r];
            unsigned idx = ~(unsigned)key;
            size_t off = ((size_t)b * NPTS + idx) * 4;
            float a0 = anchors[off + 0], a1 = anchors[off + 1];
            float a2 = anchors[off + 2], a3 = anchors[off + 3];
            float d0 = deltas[off + 0] * 0.1f, d1 = deltas[off + 1] * 0.1f;
            float d2 = deltas[off + 2] * 0.2f, d3 = deltas[off + 3] * 0.2f;
            float w = a2 - a0, h = a3 - a1;
            float cx = a0 + 0.5f * w;
            float cy = a1 + 0.5f * h;
            cx = cx + d0 * w;
            cy = cy + d1 * h;
            w = w * expf(d2);
            h = h * expf(d3);
            box.x = fminf(fmaxf(cx - 0.5f * w, 0.f), 1.f);
            box.y = fminf(fmaxf(cy - 0.5f * h, 0.f), 1.f);
            box.z = fminf(fmaxf(cx + 0.5f * w, 0.f), 1.f);
            box.w = fminf(fmaxf(cy + 0.5f * h, 0.f), 1.f);
        }
        g_boxes[b * KTOP + r] = box;
    }
}

// ---------------- greedy NMS, chunked scan, early exit at NOUT kept ----------------
__device__ __forceinline__ bool iou_gt(float4 a, float aa, float4 c, float ac) {
    float lx = fmaxf(a.x, c.x), ly = fmaxf(a.y, c.y);
    float rx = fminf(a.z, c.z), ry = fminf(a.w, c.w);
    float iw = fmaxf(rx - lx, 0.f), ih = fmaxf(ry - ly, 0.f);
    float inter = iw * ih;
    // multiply form (avoids MUFU division); same sign as inter/denom > THR
    return inter > THR * (aa + ac - inter + 1e-12f);
}

__global__ void __launch_bounds__(NMS_T) k_nms(float* __restrict__ out) {
    __shared__ float4 s_kept[NOUT];
    __shared__ float s_karea[NOUT];
    __shared__ float4 s_chunk[64];
    __shared__ float s_carea[64];
    __shared__ unsigned long long s_intra[64];
    __shared__ unsigned long long s_sup;
    __shared__ int s_keptCount, s_newCount, s_done;
    __shared__ int s_newIdx[64];

    int b = blockIdx.x, t = threadIdx.x;
    float4* out4 = reinterpret_cast<float4*>(out) + b * NOUT;
    const float4* boxes = g_boxes + b * KTOP;

    if (t == 0) { s_keptCount = 0; s_done = 0; }

    const int nchunks = (KTOP + 63) / 64;
    for (int c = 0; c < nchunks; c++) {
        __syncthreads();
        if (s_done) break;
        int base = c * 64;
        int nc = KTOP - base;
        if (nc > 64) nc = 64;

        if (t < 64) {
            float4 bx = (t < nc) ? boxes[base + t] : make_float4(2.f, 2.f, 2.f, 2.f);
            s_chunk[t] = bx;
            s_carea[t] = (bx.z - bx.x) * (bx.w - bx.y);
            s_intra[t] = 0ULL;
        }
        if (t == 0) { s_sup = 0ULL; s_newCount = 0; }
        __syncthreads();

        int kc = s_keptCount;

        // suppressed-by-previously-kept: thread group (t>>6) strides kept list,
        // 64 lanes cover the chunk columns (s_kept read is a broadcast)
        {
            int j = t & 63;
            float4 bj = s_chunk[j];
            float aj = s_carea[j];
            bool sup = false;
            for (int k = (t >> 6); k < kc; k += (NMS_T >> 6)) {
                if (iou_gt(s_kept[k], s_karea[k], bj, aj)) { sup = true; break; }
            }
            if (sup && j < nc) atomicOr(&s_sup, 1ULL << j);
        }
        // intra-chunk 64x64 upper-triangular mask
        for (int p = t; p < 64 * 64; p += NMS_T) {
            int i = p >> 6, j = p & 63;
            if (i < j && j < nc) {
                if (iou_gt(s_chunk[i], s_carea[i], s_chunk[j], s_carea[j]))
                    atomicOr(&s_intra[i], 1ULL << j);
            }
        }
        __syncthreads();

        // sequential 64-step greedy dance (register-resident, one thread)
        if (t == 0) {
            unsigned long long removed = s_sup;
            int ncnt = 0;
            for (int i = 0; i < nc; i++) {
                if (!((removed >> i) & 1ULL)) {
                    s_newIdx[ncnt++] = i;
                    removed |= s_intra[i];
                    if (kc + ncnt == NOUT) { s_done = 1; break; }
                }
            }
            s_newCount = ncnt;
            s_keptCount = kc + ncnt;
        }
        __syncthreads();

        int ncnt = s_newCount;
        if (t < ncnt) {
            int i = s_newIdx[t];
            int rank = kc + t;
            float4 bx = s_chunk[i];
            s_kept[rank] = bx;
            s_karea[rank] = s_carea[i];
            out4[rank] = bx;
        }
    }
    __syncthreads();
    int kc = s_keptCount;
    for (int r = kc + t; r < NOUT; r += NMS_T)
        out4[r] = make_float4(0.f, 0.f, 0.f, 0.f);
}

// ---------------- launch ----------------
extern "C" void kernel_launch(void* const* d_in, const int* in_sizes, int n_in,
                              void* d_out, int out_size) {
    const float* scores  = (const float*)d_in[0];
    const float* deltas  = (const float*)d_in[1];
    const float* anchors = (const float*)d_in[2];
    float* out = (float*)d_out;

    cudaFuncSetAttribute(k_sort, cudaFuncAttributeMaxDynamicSharedMemorySize,
                         CAP * (int)sizeof(unsigned long long));

    k_zero<<<256, 256>>>();
    k_hist<<<(NB * NPTS) / 256, 256>>>(scores);
    k_cut<<<NB, 1024>>>();
    k_compact<<<(NB * NPTS) / 256, 256>>>(scores);
    k_sort<<<NB, 1024, CAP * sizeof(unsigned long long)>>>(deltas, anchors);
    k_nms<<<NB, NMS_T>>>(out);
}

// round 9
// speedup vs baseline: 2.1603x; 2.1603x over previous
#include <cuda_runtime.h>
#include <cstdint>

#define NB 4
#define NPTS 262144
#define NPTS_LOG2 18
#define KTOP 6000
#define CAP 16384
#define NOUT 1000
#define NBINS 65536
#define NSEG 32
#define SEGCAP 2048
#define NMS_T 1024
#define THR 0.7f

// ---------------- device scratch (no allocations allowed) ----------------
__device__ unsigned int g_hist[NB * NBINS];
__device__ unsigned int g_cut[NB];
__device__ unsigned int g_binbase[NB * NSEG];   // global offset of each segment
__device__ unsigned int g_bincnt[NB * NSEG];    // scatter counters per segment
__device__ unsigned long long g_cand[NB * CAP]; // segment-partitioned keys
__device__ float4 g_boxes[NB * KTOP];

// ---------------- zero histogram (graph replays reuse scratch) ----------------
__global__ void k_zero() {
    int i = blockIdx.x * blockDim.x + threadIdx.x;   // 65536 threads, uint4 each
    reinterpret_cast<uint4*>(g_hist)[i] = make_uint4(0, 0, 0, 0);
}

// ---------------- histogram of top-16 float bits of fg score ----------------
// 131072 threads, 4 independent float4 loads each (MLP=4), covers 524288 f4s.
__global__ void __launch_bounds__(256) k_hist(const float4* __restrict__ s4) {
    int tid = blockIdx.x * blockDim.x + threadIdx.x;
    float4 q[4];
#pragma unroll
    for (int u = 0; u < 4; u++) q[u] = s4[tid + u * 131072];
#pragma unroll
    for (int u = 0; u < 4; u++) {
        int v = tid + u * 131072;            // f4 index; covers points 2v, 2v+1
        int b = v >> 17;
        unsigned bin0 = __float_as_uint(q[u].y) >> 16;
        unsigned bin1 = __float_as_uint(q[u].w) >> 16;
        atomicAdd(&g_hist[b * NBINS + bin0], 1u);
        atomicAdd(&g_hist[b * NBINS + bin1], 1u);
    }
}

// ---------------- exact cutoff bin + segment offsets ----------------
__global__ void k_cut() {
    __shared__ unsigned csum[1024];
    __shared__ unsigned sh64[64];
    __shared__ unsigned hv[NSEG];
    __shared__ unsigned s_cc, s_runAbove, s_cut, s_sufcut;
    int b = blockIdx.x, t = threadIdx.x;
    const unsigned* h = &g_hist[b * NBINS];

    // per-64-bin chunk sums, coalesced loads + warp reduce
    int w = t >> 5, lane = t & 31;
    for (int ct = w; ct < 1024; ct += 32) {
        unsigned v = h[ct * 64 + lane] + h[ct * 64 + 32 + lane];
        unsigned tot = __reduce_add_sync(0xffffffffu, v);
        if (lane == 0) csum[ct] = tot;
    }
    __syncthreads();

    if (t == 0) {
        unsigned run = 0; int cc = 0;
        for (int c = 1023; c >= 0; c--) {
            if (run + csum[c] >= KTOP) { cc = c; break; }
            run += csum[c];
        }
        s_cc = (unsigned)cc; s_runAbove = run;
    }
    __syncthreads();
    int cc = (int)s_cc;
    if (t < 64) sh64[t] = h[cc * 64 + t];
    __syncthreads();
    if (t == 0) {
        unsigned run = s_runAbove, cut = (unsigned)(cc * 64);
        for (int j = 63; j >= 0; j--) {
            run += sh64[j];
            if (run >= KTOP) { cut = (unsigned)(cc * 64 + j); break; }
        }
        s_cut = cut; s_sufcut = run;      // run = suffix(cut) >= KTOP
        g_cut[b] = cut;
    }
    __syncthreads();
    unsigned cut = s_cut;
    if (t < NSEG) {
        hv[t] = (cut + t < NBINS) ? h[cut + t] : 0u;
        g_bincnt[b * NSEG + t] = 0;
    }
    __syncthreads();
    if (t == 0) {
        unsigned suf = s_sufcut;          // suffix(cut)
        for (int s = 0; s < NSEG; s++) {  // binbase[s] = suffix(cut+s+1)
            suf -= hv[s];
            g_binbase[b * NSEG + s] = suf;
        }
    }
}

// ---------------- compact: scatter candidates straight into rank segments ----------------
__device__ __forceinline__ void compact_one(int b, unsigned i, unsigned bits) {
    unsigned bin = bits >> 16;
    unsigned cut = g_cut[b];
    if (bin >= cut) {
        unsigned s = bin - cut;
        if (s < NSEG) {
            unsigned pos = g_binbase[b * NSEG + s] + atomicAdd(&g_bincnt[b * NSEG + s], 1u);
            if (pos < CAP)
                g_cand[b * CAP + pos] = ((unsigned long long)bits << 32) | (unsigned)(~i);
        }
    }
}

__global__ void __launch_bounds__(256) k_compact(const float4* __restrict__ s4) {
    int tid = blockIdx.x * blockDim.x + threadIdx.x;
    float4 q[4];
#pragma unroll
    for (int u = 0; u < 4; u++) q[u] = s4[tid + u * 131072];
#pragma unroll
    for (int u = 0; u < 4; u++) {
        int v = tid + u * 131072;
        int b = v >> 17;
        unsigned i0 = (unsigned)(2 * v) & (NPTS - 1);
        compact_one(b, i0,     __float_as_uint(q[u].y));
        compact_one(b, i0 + 1, __float_as_uint(q[u].w));
    }
}

// ---------------- per-segment bitonic sort (<=2048 keys) + box decode ----------------
__global__ void __launch_bounds__(256) k_segsort(const float4* __restrict__ deltas4,
                                                 const float4* __restrict__ anchors4) {
    __shared__ unsigned long long sk[SEGCAP];
    int b = blockIdx.x / NSEG, s = blockIdx.x % NSEG, t = threadIdx.x;
    unsigned base = g_binbase[b * NSEG + s];
    unsigned n = g_bincnt[b * NSEG + s];
    if (n > SEGCAP) n = SEGCAP;
    if (n == 0 || base >= KTOP) return;   // empty or entirely beyond top-K

    for (int i = t; i < SEGCAP; i += 256)
        sk[i] = (i < (int)n) ? g_cand[b * CAP + base + i] : 0ULL;
    __syncthreads();

    for (int k = 2; k <= SEGCAP; k <<= 1) {
        for (int j = k >> 1; j > 0; j >>= 1) {
            for (int i = t; i < SEGCAP; i += 256) {
                int ixj = i ^ j;
                if (ixj > i) {
                    unsigned long long a = sk[i], c = sk[ixj];
                    bool sw = ((i & k) == 0) ? (a < c) : (a > c);  // descending
                    if (sw) { sk[i] = c; sk[ixj] = a; }
                }
            }
            __syncthreads();
        }
    }

    // decode the segment's boxes into their global ranks (< KTOP)
    int lim = (int)n;
    if ((int)(KTOP - base) < lim) lim = (int)(KTOP - base);
    for (int r = t; r < lim; r += 256) {
        unsigned idx = ~(unsigned)sk[r];
        size_t off = (size_t)b * NPTS + idx;
        float4 aa = anchors4[off];
        float4 dd = deltas4[off];
        float d0 = dd.x * 0.1f, d1 = dd.y * 0.1f, d2 = dd.z * 0.2f, d3 = dd.w * 0.2f;
        float w = aa.z - aa.x, h = aa.w - aa.y;
        float cx = aa.x + 0.5f * w + d0 * w;
        float cy = aa.y + 0.5f * h + d1 * h;
        w = w * expf(d2);
        h = h * expf(d3);
        float4 box;
        box.x = fminf(fmaxf(cx - 0.5f * w, 0.f), 1.f);
        box.y = fminf(fmaxf(cy - 0.5f * h, 0.f), 1.f);
        box.z = fminf(fmaxf(cx + 0.5f * w, 0.f), 1.f);
        box.w = fminf(fmaxf(cy + 0.5f * h, 0.f), 1.f);
        g_boxes[b * KTOP + base + r] = box;
    }
}

// ---------------- greedy NMS, chunked scan, early exit at NOUT kept ----------------
__device__ __forceinline__ bool iou_gt(float4 a, float aa, float4 c, float ac) {
    float lx = fmaxf(a.x, c.x), ly = fmaxf(a.y, c.y);
    float rx = fminf(a.z, c.z), ry = fminf(a.w, c.w);
    float iw = fmaxf(rx - lx, 0.f), ih = fmaxf(ry - ly, 0.f);
    float inter = iw * ih;
    return inter > THR * (aa + ac - inter + 1e-12f);   // multiply form, no MUFU div
}

__global__ void __launch_bounds__(NMS_T) k_nms(float* __restrict__ out) {
    __shared__ float4 s_kept[NOUT];
    __shared__ float s_karea[NOUT];
    __shared__ float4 s_chunk[64];
    __shared__ float s_carea[64];
    __shared__ unsigned long long s_intra[65];   // +1 pad for prefetch
    __shared__ unsigned long long s_sup;
    __shared__ int s_keptCount, s_newCount, s_done;
    __shared__ int s_newIdx[64];

    int b = blockIdx.x, t = threadIdx.x;
    float4* out4 = reinterpret_cast<float4*>(out) + b * NOUT;
    const float4* boxes = g_boxes + b * KTOP;

    if (t == 0) { s_keptCount = 0; s_done = 0; }

    const int nchunks = (KTOP + 63) / 64;
    for (int c = 0; c < nchunks; c++) {
        __syncthreads();
        if (s_done) break;
        int base = c * 64;
        int nc = KTOP - base;
        if (nc > 64) nc = 64;

        if (t < 64) {
            float4 bx = (t < nc) ? boxes[base + t] : make_float4(2.f, 2.f, 2.f, 2.f);
            s_chunk[t] = bx;
            s_carea[t] = (bx.z - bx.x) * (bx.w - bx.y);
            s_intra[t] = 0ULL;
        }
        if (t == 0) { s_sup = 0ULL; s_newCount = 0; s_intra[64] = 0ULL; }
        __syncthreads();

        int kc = s_keptCount;

        // suppressed-by-kept: 16 thread-groups stride the kept list, 64 lanes = chunk cols
        {
            int j = t & 63;
            float4 bj = s_chunk[j];
            float aj = s_carea[j];
            unsigned sup = 0;
#pragma unroll 4
            for (int k = (t >> 6); k < kc; k += (NMS_T >> 6))
                sup |= (unsigned)iou_gt(s_kept[k], s_karea[k], bj, aj);
            if (sup && j < nc) atomicOr(&s_sup, 1ULL << j);
        }
        // intra-chunk 64x64 upper-triangular mask
        for (int p = t; p < 64 * 64; p += NMS_T) {
            int i = p >> 6, j = p & 63;
            if (i < j && j < nc) {
                if (iou_gt(s_chunk[i], s_carea[i], s_chunk[j], s_carea[j]))
                    atomicOr(&s_intra[i], 1ULL << j);
            }
        }
        __syncthreads();

        // serial greedy over 64 bits, smem load latency hidden by prefetch
        if (t == 0) {
            unsigned long long removed = s_sup;
            unsigned long long cur = s_intra[0];
            int ncnt = 0;
            for (int i = 0; i < nc; i++) {
                unsigned long long nxt = s_intra[i + 1];
                if (!((removed >> i) & 1ULL)) {
                    s_newIdx[ncnt++] = i;
                    removed |= cur;
                    if (kc + ncnt == NOUT) { s_done = 1; break; }
                }
                cur = nxt;
            }
            s_newCount = ncnt;
            s_keptCount = kc + ncnt;
        }
        __syncthreads();

        int ncnt = s_newCount;
        if (t < ncnt) {
            int i = s_newIdx[t];
            int rank = kc + t;
            float4 bx = s_chunk[i];
            s_kept[rank] = bx;
            s_karea[rank] = s_carea[i];
            out4[rank] = bx;
        }
    }
    __syncthreads();
    int kc = s_keptCount;
    for (int r = kc + t; r < NOUT; r += NMS_T)
        out4[r] = make_float4(0.f, 0.f, 0.f, 0.f);
}

// ---------------- launch ----------------
extern "C" void kernel_launch(void* const* d_in, const int* in_sizes, int n_in,
                              void* d_out, int out_size) {
    const float4* scores4  = (const float4*)d_in[0];
    const float4* deltas4  = (const float4*)d_in[1];
    const float4* anchors4 = (const float4*)d_in[2];
    float* out = (float*)d_out;

    k_zero<<<256, 256>>>();
    k_hist<<<512, 256>>>(scores4);
    k_cut<<<NB, 1024>>>();
    k_compact<<<512, 256>>>(scores4);
    k_segsort<<<NB * NSEG, 256>>>(deltas4, anchors4);
    k_nms<<<NB, NMS_T>>>(out);
}

// round 11
// speedup vs baseline: 2.4141x; 1.1175x over previous
#include <cuda_runtime.h>
#include <cstdint>

#define NB 4
#define NPTS 262144
#define NPTS_LOG2 18
#define KTOP 6000
#define CAP 16384
#define NOUT 1000
#define NBINS 65536
#define NSEG 32
#define SEGCAP 2048
#define SMASK 2048           // rows covered by precomputed mask
#define MWORDS 32            // SMASK/64 suppression words per row
#define NMS_T 1024
#define THR 0.7f

// ---------------- device scratch (no allocations allowed) ----------------
__device__ unsigned int g_hist[NB * NBINS];
__device__ unsigned int g_cut[NB];
__device__ unsigned int g_binbase[NB * NSEG];
__device__ unsigned int g_bincnt[NB * NSEG];
__device__ unsigned long long g_cand[NB * CAP];
__device__ float4 g_boxes[NB * KTOP];
__device__ unsigned long long g_mask[NB * SMASK * MWORDS];  // 2MB, L2-resident
__device__ int g_kc[NB];
__device__ int g_doneflag[NB];

// ---------------- zero histogram (graph replays reuse scratch) ----------------
__global__ void k_zero() {
    int i = blockIdx.x * blockDim.x + threadIdx.x;   // 65536 threads, uint4 each
    reinterpret_cast<uint4*>(g_hist)[i] = make_uint4(0, 0, 0, 0);
}

// ---------------- histogram of top-16 float bits of fg score ----------------
// 524288 threads, one float4 each (two fg scores per thread).
__global__ void __launch_bounds__(256) k_hist(const float4* __restrict__ s4) {
    int tid = blockIdx.x * blockDim.x + threadIdx.x;
    float4 q = s4[tid];
    int b = tid >> 17;
    atomicAdd(&g_hist[b * NBINS + (__float_as_uint(q.y) >> 16)], 1u);
    atomicAdd(&g_hist[b * NBINS + (__float_as_uint(q.w) >> 16)], 1u);
}

// ---------------- exact cutoff bin + segment offsets ----------------
__global__ void k_cut() {
    __shared__ unsigned csum[1024];
    __shared__ unsigned sh64[64];
    __shared__ unsigned hv[NSEG];
    __shared__ unsigned s_cc, s_runAbove, s_cut, s_sufcut;
    int b = blockIdx.x, t = threadIdx.x;
    const unsigned* h = &g_hist[b * NBINS];

    int w = t >> 5, lane = t & 31;
    for (int ct = w; ct < 1024; ct += 32) {
        unsigned v = h[ct * 64 + lane] + h[ct * 64 + 32 + lane];
        unsigned tot = __reduce_add_sync(0xffffffffu, v);
        if (lane == 0) csum[ct] = tot;
    }
    __syncthreads();

    if (t == 0) {
        unsigned run = 0; int cc = 0;
        for (int c = 1023; c >= 0; c--) {
            if (run + csum[c] >= KTOP) { cc = c; break; }
            run += csum[c];
        }
        s_cc = (unsigned)cc; s_runAbove = run;
    }
    __syncthreads();
    int cc = (int)s_cc;
    if (t < 64) sh64[t] = h[cc * 64 + t];
    __syncthreads();
    if (t == 0) {
        unsigned run = s_runAbove, cut = (unsigned)(cc * 64);
        for (int j = 63; j >= 0; j--) {
            run += sh64[j];
            if (run >= KTOP) { cut = (unsigned)(cc * 64 + j); break; }
        }
        s_cut = cut; s_sufcut = run;
        g_cut[b] = cut;
    }
    __syncthreads();
    unsigned cut = s_cut;
    if (t < NSEG) {
        hv[t] = (cut + t < NBINS) ? h[cut + t] : 0u;
        g_bincnt[b * NSEG + t] = 0;
    }
    __syncthreads();
    if (t == 0) {
        unsigned suf = s_sufcut;
        for (int s = 0; s < NSEG; s++) {
            suf -= hv[s];
            g_binbase[b * NSEG + s] = suf;
        }
    }
}

// ---------------- compact: scatter candidates straight into rank segments ----------------
__device__ __forceinline__ void compact_one(int b, unsigned i, unsigned bits) {
    unsigned bin = bits >> 16;
    unsigned cut = g_cut[b];
    if (bin >= cut) {
        unsigned s = bin - cut;
        if (s < NSEG) {
            unsigned pos = g_binbase[b * NSEG + s] + atomicAdd(&g_bincnt[b * NSEG + s], 1u);
            if (pos < CAP)
                g_cand[b * CAP + pos] = ((unsigned long long)bits << 32) | (unsigned)(~i);
        }
    }
}

__global__ void __launch_bounds__(256) k_compact(const float4* __restrict__ s4) {
    int tid = blockIdx.x * blockDim.x + threadIdx.x;
    float4 q = s4[tid];
    int b = tid >> 17;
    unsigned i0 = (unsigned)(2 * tid) & (NPTS - 1);
    compact_one(b, i0,     __float_as_uint(q.y));
    compact_one(b, i0 + 1, __float_as_uint(q.w));
}

// ---------------- per-segment bitonic sort (<=2048 keys) + box decode ----------------
__global__ void __launch_bounds__(256) k_segsort(const float4* __restrict__ deltas4,
                                                 const float4* __restrict__ anchors4) {
    __shared__ unsigned long long sk[SEGCAP];
    int b = blockIdx.x / NSEG, s = blockIdx.x % NSEG, t = threadIdx.x;
    unsigned base = g_binbase[b * NSEG + s];
    unsigned n = g_bincnt[b * NSEG + s];
    if (n > SEGCAP) n = SEGCAP;
    if (n == 0 || base >= KTOP) return;

    for (int i = t; i < SEGCAP; i += 256)
        sk[i] = (i < (int)n) ? g_cand[b * CAP + base + i] : 0ULL;
    __syncthreads();

    for (int k = 2; k <= SEGCAP; k <<= 1) {
        for (int j = k >> 1; j > 0; j >>= 1) {
            for (int i = t; i < SEGCAP; i += 256) {
                int ixj = i ^ j;
                if (ixj > i) {
                    unsigned long long a = sk[i], c = sk[ixj];
                    bool sw = ((i & k) == 0) ? (a < c) : (a > c);  // descending
                    if (sw) { sk[i] = c; sk[ixj] = a; }
                }
            }
            __syncthreads();
        }
    }

    int lim = (int)n;
    if ((int)(KTOP - base) < lim) lim = (int)(KTOP - base);
    for (int r = t; r < lim; r += 256) {
        unsigned idx = ~(unsigned)sk[r];
        size_t off = (size_t)b * NPTS + idx;
        float4 aa = anchors4[off];
        float4 dd = deltas4[off];
        float d0 = dd.x * 0.1f, d1 = dd.y * 0.1f, d2 = dd.z * 0.2f, d3 = dd.w * 0.2f;
        float w = aa.z - aa.x, h = aa.w - aa.y;
        float cx = aa.x + 0.5f * w + d0 * w;
        float cy = aa.y + 0.5f * h + d1 * h;
        w = w * expf(d2);
        h = h * expf(d3);
        float4 box;
        box.x = fminf(fmaxf(cx - 0.5f * w, 0.f), 1.f);
        box.y = fminf(fmaxf(cy - 0.5f * h, 0.f), 1.f);
        box.z = fminf(fmaxf(cx + 0.5f * w, 0.f), 1.f);
        box.w = fminf(fmaxf(cy + 0.5f * h, 0.f), 1.f);
        g_boxes[b * KTOP + base + r] = box;
    }
}

// ---------------- IoU comparator (multiply form, no MUFU div) ----------------
__device__ __forceinline__ bool iou_gt(float4 a, float aa, float4 c, float ac) {
    float lx = fmaxf(a.x, c.x), ly = fmaxf(a.y, c.y);
    float rx = fminf(a.z, c.z), ry = fminf(a.w, c.w);
    float iw = fmaxf(rx - lx, 0.f), ih = fmaxf(ry - ly, 0.f);
    float inter = iw * ih;
    return inter > THR * (aa + ac - inter + 1e-12f);
}

// ---------------- parallel mask build: 64x64 tiles, upper triangle only ----------------
// grid (tj=x in 0..31, ti=y in 0..31, b=z), 256 threads: lane i covers a row,
// group q covers 16 cols. Bit set iff IoU>thr and global col > global row.
__global__ void __launch_bounds__(256) k_mask() {
    int tj = blockIdx.x, ti = blockIdx.y, b = blockIdx.z;
    if (tj < ti) return;
    __shared__ float4 s_rb[64]; __shared__ float s_ra[64];
    __shared__ float4 s_cb[64]; __shared__ float s_ca[64];
    __shared__ unsigned long long s_word[64];
    int t = threadIdx.x;
    const float4* boxes = g_boxes + b * KTOP;
    if (t < 64) {
        float4 r = boxes[ti * 64 + t];
        s_rb[t] = r; s_ra[t] = (r.z - r.x) * (r.w - r.y);
        s_word[t] = 0ULL;
    } else if (t < 128) {
        int j = t - 64;
        float4 c = boxes[tj * 64 + j];
        s_cb[j] = c; s_ca[j] = (c.z - c.x) * (c.w - c.y);
    }
    __syncthreads();
    int i = t & 63, q = t >> 6;
    float4 bi = s_rb[i]; float ai = s_ra[i];
    unsigned long long part = 0ULL;
#pragma unroll
    for (int jj = 0; jj < 16; jj++) {
        int j = q * 16 + jj;
        bool fwd = (ti < tj) || (j > i);
        if (fwd && iou_gt(bi, ai, s_cb[j], s_ca[j]))
            part |= 1ULL << j;
    }
    if (part) atomicOr(&s_word[i], part);
    __syncthreads();
    if (t < 64)
        g_mask[((size_t)b * SMASK + ti * 64 + t) * MWORDS + tj] = s_word[t];
}

// ---------------- fast greedy over precomputed mask (first SMASK rows) ----------------
__global__ void __launch_bounds__(NMS_T) k_greedy(float* __restrict__ out) {
    __shared__ unsigned long long s_diag[SMASK + 8];
    __shared__ unsigned long long s_removed[MWORDS];
    __shared__ int s_keptIdx[NOUT];
    __shared__ int s_kc, s_kcOld, s_done;

    int b = blockIdx.x, t = threadIdx.x;
    const unsigned long long* mask = g_mask + (size_t)b * SMASK * MWORDS;
    float4* out4 = reinterpret_cast<float4*>(out) + b * NOUT;

    for (int p = t; p < SMASK; p += NMS_T)
        s_diag[p] = mask[(size_t)p * MWORDS + (p >> 6)];
    if (t < MWORDS) s_removed[t] = 0ULL;
    if (t == 0) { s_kc = 0; s_done = 0; s_diag[SMASK] = 0ULL; }

    for (int c = 0; c < MWORDS; c++) {
        __syncthreads();                       // removed ORs from prev chunk visible
        if (t == 0) {
            unsigned long long removed = s_removed[c];
            int kc = s_kc;
            s_kcOld = kc;
            unsigned long long cur = s_diag[c * 64];
            for (int i = 0; i < 64; i++) {
                unsigned long long nxt = s_diag[c * 64 + i + 1];
                if (!((removed >> i) & 1ULL)) {
                    s_keptIdx[kc++] = c * 64 + i;
                    removed |= cur;
                    if (kc == NOUT) { s_done = 1; break; }
                }
                cur = nxt;
            }
            s_kc = kc;
        }
        __syncthreads();
        if (s_done) break;
        int kcOld = s_kcOld, ncnt = s_kc - kcOld;
        for (int p = t; p < ncnt * MWORDS; p += NMS_T) {
            int k = p >> 5, w = p & (MWORDS - 1);
            int row = s_keptIdx[kcOld + k];
            unsigned long long m = mask[(size_t)row * MWORDS + w];
            if (m) atomicOr(&s_removed[w], m);
        }
    }
    __syncthreads();
    int kc = s_kc;
    if (t == 0) { g_kc[b] = kc; g_doneflag[b] = (kc == NOUT); }
    for (int r = t; r < kc; r += NMS_T)
        out4[r] = g_boxes[b * KTOP + s_keptIdx[r]];
}

// ---------------- fallback: continue on-the-fly NMS from row SMASK (rare) ----------------
__global__ void __launch_bounds__(NMS_T) k_nms_tail(float* __restrict__ out) {
    __shared__ float4 s_kept[NOUT];
    __shared__ float s_karea[NOUT];
    __shared__ float4 s_chunk[64];
    __shared__ float s_carea[64];
    __shared__ unsigned long long s_intra[65];
    __shared__ unsigned long long s_sup;
    __shared__ int s_keptCount, s_newCount, s_done;
    __shared__ int s_newIdx[64];

    int b = blockIdx.x, t = threadIdx.x;
    if (g_doneflag[b]) return;                 // normal case: done in k_greedy

    float4* out4 = reinterpret_cast<float4*>(out) + b * NOUT;
    const float4* boxes = g_boxes + b * KTOP;
    int kc0 = g_kc[b];

    for (int r = t; r < kc0; r += NMS_T) {
        float4 bx = out4[r];
        s_kept[r] = bx;
        s_karea[r] = (bx.z - bx.x) * (bx.w - bx.y);
    }
    if (t == 0) { s_keptCount = kc0; s_done = 0; }

    const int nchunks = (KTOP + 63) / 64;
    for (int c = SMASK / 64; c < nchunks; c++) {
        __syncthreads();
        if (s_done) break;
        int base = c * 64;
        int nc = KTOP - base;
        if (nc > 64) nc = 64;

        if (t < 64) {
            float4 bx = (t < nc) ? boxes[base + t] : make_float4(2.f, 2.f, 2.f, 2.f);
            s_chunk[t] = bx;
            s_carea[t] = (bx.z - bx.x) * (bx.w - bx.y);
            s_intra[t] = 0ULL;
        }
        if (t == 0) { s_sup = 0ULL; s_newCount = 0; s_intra[64] = 0ULL; }
        __syncthreads();

        int kc = s_keptCount;
        {
            int j = t & 63;
            float4 bj = s_chunk[j];
            float aj = s_carea[j];
            unsigned sup = 0;
#pragma unroll 4
            for (int k = (t >> 6); k < kc; k += (NMS_T >> 6))
                sup |= (unsigned)iou_gt(s_kept[k], s_karea[k], bj, aj);
            if (sup && j < nc) atomicOr(&s_sup, 1ULL << j);
        }
        for (int p = t; p < 64 * 64; p += NMS_T) {
            int i = p >> 6, j = p & 63;
            if (i < j && j < nc) {
                if (iou_gt(s_chunk[i], s_carea[i], s_chunk[j], s_carea[j]))
                    atomicOr(&s_intra[i], 1ULL << j);
            }
        }
        __syncthreads();

        if (t == 0) {
            unsigned long long removed = s_sup;
            unsigned long long cur = s_intra[0];
            int ncnt = 0;
            for (int i = 0; i < nc; i++) {
                unsigned long long nxt = s_intra[i + 1];
                if (!((removed >> i) & 1ULL)) {
                    s_newIdx[ncnt++] = i;
                    removed |= cur;
                    if (kc + ncnt == NOUT) { s_done = 1; break; }
                }
                cur = nxt;
            }
            s_newCount = ncnt;
            s_keptCount = kc + ncnt;
        }
        __syncthreads();

        int ncnt = s_newCount;
        if (t < ncnt) {
            int i = s_newIdx[t];
            int rank = kc + t;
            float4 bx = s_chunk[i];
            s_kept[rank] = bx;
            s_karea[rank] = s_carea[i];
            out4[rank] = bx;
        }
    }
    __syncthreads();
    int kc = s_keptCount;
    for (int r = kc + t; r < NOUT; r += NMS_T)
        out4[r] = make_float4(0.f, 0.f, 0.f, 0.f);
}

// ---------------- launch ----------------
extern "C" void kernel_launch(void* const* d_in, const int* in_sizes, int n_in,
                              void* d_out, int out_size) {
    const float4* scores4  = (const float4*)d_in[0];
    const float4* deltas4  = (const float4*)d_in[1];
    const float4* anchors4 = (const float4*)d_in[2];
    float* out = (float*)d_out;

    k_zero<<<256, 256>>>();
    k_hist<<<2048, 256>>>(scores4);
    k_cut<<<NB, 1024>>>();
    k_compact<<<2048, 256>>>(scores4);
    k_segsort<<<NB * NSEG, 256>>>(deltas4, anchors4);
    k_mask<<<dim3(32, 32, NB), 256>>>();
    k_greedy<<<NB, NMS_T>>>(out);
    k_nms_tail<<<NB, NMS_T>>>(out);
}